// round 1
// baseline (speedup 1.0000x reference)
#include <cuda_runtime.h>
#include <cuda_bf16.h>
#include <math.h>

#define D_  1024
#define S_  2048
#define H_  16
#define HD_ 64
#define B_  2
#define M_  (B_ * S_)   // 4096 rows for projection GEMMs

// Scratch: Q,K,V in [B,H,S,HD] layout, ctx in [B,S,D] layout.
__device__ float g_q[B_ * H_ * S_ * HD_];
__device__ float g_k[B_ * H_ * S_ * HD_];
__device__ float g_v[B_ * H_ * S_ * HD_];
__device__ float g_ctx[M_ * D_];

// ---------------------------------------------------------------------------
// GEMM: C = A[M,1024] @ W[1024,1024] + bias
// MODE 0: C row-major [M, D]
// MODE 1: C scattered into [B, H, S, HD] (head-split layout)
// Block tile 64x64, K-step 16, 256 threads, 4x4 accum per thread.
// ---------------------------------------------------------------------------
template <int MODE>
__global__ void gemm64_bias(const float* __restrict__ A,
                            const float* __restrict__ W,
                            const float* __restrict__ bias,
                            float* __restrict__ C) {
    __shared__ float sA[64][16];
    __shared__ float sB[16][64];

    const int tid = threadIdx.x;
    const int tx = tid & 15;        // 0..15
    const int ty = tid >> 4;        // 0..15
    const int row0 = blockIdx.y * 64;
    const int col0 = blockIdx.x * 64;

    // load indexing
    const int arow = tid >> 2;          // 0..63
    const int acol = (tid & 3) * 4;     // 0,4,8,12
    const int brow = tid >> 4;          // 0..15
    const int bcol = (tid & 15) * 4;    // 0..60

    float acc[4][4];
#pragma unroll
    for (int r = 0; r < 4; r++)
#pragma unroll
        for (int c = 0; c < 4; c++) acc[r][c] = 0.0f;

    for (int k0 = 0; k0 < D_; k0 += 16) {
        float4 av = *reinterpret_cast<const float4*>(
            &A[(size_t)(row0 + arow) * D_ + k0 + acol]);
        *reinterpret_cast<float4*>(&sA[arow][acol]) = av;

        float4 bv = *reinterpret_cast<const float4*>(
            &W[(size_t)(k0 + brow) * D_ + col0 + bcol]);
        *reinterpret_cast<float4*>(&sB[brow][bcol]) = bv;

        __syncthreads();

#pragma unroll
        for (int kk = 0; kk < 16; kk++) {
            float a[4], b[4];
#pragma unroll
            for (int r = 0; r < 4; r++) a[r] = sA[ty * 4 + r][kk];
#pragma unroll
            for (int c = 0; c < 4; c++) b[c] = sB[kk][tx * 4 + c];
#pragma unroll
            for (int r = 0; r < 4; r++)
#pragma unroll
                for (int c = 0; c < 4; c++) acc[r][c] = fmaf(a[r], b[c], acc[r][c]);
        }
        __syncthreads();
    }

#pragma unroll
    for (int r = 0; r < 4; r++) {
        const int row = row0 + ty * 4 + r;
#pragma unroll
        for (int c = 0; c < 4; c++) {
            const int col = col0 + tx * 4 + c;
            const float val = acc[r][c] + bias[col];
            if (MODE == 0) {
                C[(size_t)row * D_ + col] = val;
            } else {
                const int bb = row >> 11;        // row / S_
                const int ss = row & (S_ - 1);
                const int hh = col >> 6;         // col / HD_
                const int dd = col & (HD_ - 1);
                C[(((size_t)(bb * H_ + hh)) * S_ + ss) * HD_ + dd] = val;
            }
        }
    }
}

// ---------------------------------------------------------------------------
// Flash attention (fp32): one block per (b, h, 64-query tile).
// Q tile in smem; K tile stored transposed; V reuses K buffer.
// 256 threads, each owns a 4x4 patch of the 64x64 score / output tile.
// ---------------------------------------------------------------------------
__global__ void attn_kernel(const float* __restrict__ Q,
                            const float* __restrict__ K,
                            const float* __restrict__ V,
                            float* __restrict__ ctx) {
    __shared__ float sQ[64][64];
    __shared__ float sKV[64][64];   // K transposed during QK; V normal during PV
    __shared__ float sP[64][64];

    const int tid = threadIdx.x;
    const int tx = tid & 15;
    const int ty = tid >> 4;
    const int qt = blockIdx.x;
    const int h  = blockIdx.y;
    const int b  = blockIdx.z;

    const size_t bh = ((size_t)b * H_ + h) * S_;
    const float* qptr = Q + (bh + (size_t)qt * 64) * HD_;

    // load Q tile (64x64 floats; 1024 float4s over 256 threads)
#pragma unroll
    for (int i = 0; i < 4; i++) {
        const int lin = tid + i * 256;
        const int r = lin >> 4;
        const int c = (lin & 15) * 4;
        *reinterpret_cast<float4*>(&sQ[r][c]) =
            *reinterpret_cast<const float4*>(&qptr[r * HD_ + c]);
    }

    float m[4], l[4], acc[4][4];
#pragma unroll
    for (int r = 0; r < 4; r++) {
        m[r] = -INFINITY;
        l[r] = 0.0f;
#pragma unroll
        for (int c = 0; c < 4; c++) acc[r][c] = 0.0f;
    }

    const float scale = 0.125f;  // 1/sqrt(64)

    for (int kt = 0; kt < S_ / 64; kt++) {
        __syncthreads();  // previous PV reads done; Q load done (first iter)

        // load K tile transposed: sKV[d][j]
        const float* kptr = K + (bh + (size_t)kt * 64) * HD_;
#pragma unroll
        for (int i = 0; i < 4; i++) {
            const int lin = tid + i * 256;
            const int r = lin >> 4;          // key row j
            const int c = (lin & 15) * 4;    // dim d
            float4 kv = *reinterpret_cast<const float4*>(&kptr[r * HD_ + c]);
            sKV[c + 0][r] = kv.x;
            sKV[c + 1][r] = kv.y;
            sKV[c + 2][r] = kv.z;
            sKV[c + 3][r] = kv.w;
        }
        __syncthreads();

        // scores: s[r][c] = sum_d Q[4ty+r][d] * K[4tx+c][d]
        float s[4][4];
#pragma unroll
        for (int r = 0; r < 4; r++)
#pragma unroll
            for (int c = 0; c < 4; c++) s[r][c] = 0.0f;

#pragma unroll 16
        for (int d = 0; d < 64; d++) {
            float a[4], bb[4];
#pragma unroll
            for (int r = 0; r < 4; r++) a[r] = sQ[ty * 4 + r][d];
#pragma unroll
            for (int c = 0; c < 4; c++) bb[c] = sKV[d][tx * 4 + c];
#pragma unroll
            for (int r = 0; r < 4; r++)
#pragma unroll
                for (int c = 0; c < 4; c++) s[r][c] = fmaf(a[r], bb[c], s[r][c]);
        }

        // online softmax update
        float mnew[4], sc[4], psum[4];
#pragma unroll
        for (int r = 0; r < 4; r++) {
            float v0 = fmaxf(fmaxf(s[r][0], s[r][1]), fmaxf(s[r][2], s[r][3])) * scale;
#pragma unroll
            for (int off = 8; off > 0; off >>= 1)
                v0 = fmaxf(v0, __shfl_xor_sync(0xffffffffu, v0, off, 16));
            mnew[r] = fmaxf(m[r], v0);
            sc[r] = __expf(m[r] - mnew[r]);
            psum[r] = 0.0f;
#pragma unroll
            for (int c = 0; c < 4; c++) {
                const float p = __expf(s[r][c] * scale - mnew[r]);
                sP[ty * 4 + r][tx * 4 + c] = p;
                psum[r] += p;
            }
#pragma unroll
            for (int off = 8; off > 0; off >>= 1)
                psum[r] += __shfl_xor_sync(0xffffffffu, psum[r], off, 16);
            l[r] = l[r] * sc[r] + psum[r];
            m[r] = mnew[r];
#pragma unroll
            for (int c = 0; c < 4; c++) acc[r][c] *= sc[r];
        }
        __syncthreads();  // sP complete; sKV (K) reads complete

        // load V tile (normal layout) into sKV
        const float* vptr = V + (bh + (size_t)kt * 64) * HD_;
#pragma unroll
        for (int i = 0; i < 4; i++) {
            const int lin = tid + i * 256;
            const int r = lin >> 4;
            const int c = (lin & 15) * 4;
            *reinterpret_cast<float4*>(&sKV[r][c]) =
                *reinterpret_cast<const float4*>(&vptr[r * HD_ + c]);
        }
        __syncthreads();

        // acc[r][c] += sum_j P[4ty+r][j] * V[j][4tx+c]
#pragma unroll 16
        for (int j = 0; j < 64; j++) {
            float pv[4], vv[4];
#pragma unroll
            for (int r = 0; r < 4; r++) pv[r] = sP[ty * 4 + r][j];
#pragma unroll
            for (int c = 0; c < 4; c++) vv[c] = sKV[j][tx * 4 + c];
#pragma unroll
            for (int r = 0; r < 4; r++)
#pragma unroll
                for (int c = 0; c < 4; c++) acc[r][c] = fmaf(pv[r], vv[c], acc[r][c]);
        }
    }

    // write ctx in [B, S, D] layout
#pragma unroll
    for (int r = 0; r < 4; r++) {
        const float inv_l = 1.0f / l[r];
        const size_t row = (size_t)b * S_ + (size_t)qt * 64 + ty * 4 + r;
#pragma unroll
        for (int c = 0; c < 4; c++) {
            ctx[row * D_ + h * HD_ + tx * 4 + c] = acc[r][c] * inv_l;
        }
    }
}

// ---------------------------------------------------------------------------
extern "C" void kernel_launch(void* const* d_in, const int* in_sizes, int n_in,
                              void* d_out, int out_size) {
    const float* x  = (const float*)d_in[0];
    const float* Wq = (const float*)d_in[1];
    const float* bq = (const float*)d_in[2];
    const float* Wk = (const float*)d_in[3];
    const float* bk = (const float*)d_in[4];
    const float* Wv = (const float*)d_in[5];
    const float* bv = (const float*)d_in[6];
    const float* Wo = (const float*)d_in[7];
    const float* bo = (const float*)d_in[8];
    float* out = (float*)d_out;

    float *q, *k, *v, *ctx;
    cudaGetSymbolAddress((void**)&q,   g_q);
    cudaGetSymbolAddress((void**)&k,   g_k);
    cudaGetSymbolAddress((void**)&v,   g_v);
    cudaGetSymbolAddress((void**)&ctx, g_ctx);

    dim3 gemm_grid(D_ / 64, M_ / 64);   // (16, 64)
    dim3 gemm_blk(256);

    gemm64_bias<1><<<gemm_grid, gemm_blk>>>(x, Wq, bq, q);
    gemm64_bias<1><<<gemm_grid, gemm_blk>>>(x, Wk, bk, k);
    gemm64_bias<1><<<gemm_grid, gemm_blk>>>(x, Wv, bv, v);

    dim3 attn_grid(S_ / 64, H_, B_);    // (32, 16, 2)
    attn_kernel<<<attn_grid, gemm_blk>>>(q, k, v, ctx);

    gemm64_bias<0><<<gemm_grid, gemm_blk>>>(ctx, Wo, bo, out);
}

// round 3
// speedup vs baseline: 1.4777x; 1.4777x over previous
#include <cuda_runtime.h>
#include <math.h>
#include <cstdint>

#define D_  1024
#define S_  2048
#define H_  16
#define HD_ 64
#define B_  2
#define M_  (B_ * S_)   // 4096

// Scratch
__device__ float g_q[B_ * H_ * S_ * HD_];
__device__ float g_k[B_ * H_ * S_ * HD_];
__device__ float g_v[B_ * H_ * S_ * HD_];
__device__ float g_ctx[M_ * D_];
__device__ float g_wt[4][D_ * D_];   // transposed + tf32-rounded weights [N,K]
__device__ float g_xr[M_ * D_];      // tf32-rounded x

// ---------------------------------------------------------------------------
// helpers
// ---------------------------------------------------------------------------
__device__ __forceinline__ uint32_t smem_u32(const void* p) {
    uint32_t a;
    asm("{ .reg .u64 t; cvta.to.shared.u64 t, %1; cvt.u32.u64 %0, t; }"
        : "=r"(a) : "l"(p));
    return a;
}
__device__ __forceinline__ float rna_tf32(float x) {
    uint32_t u;
    asm("cvt.rna.tf32.f32 %0, %1;" : "=r"(u) : "f"(x));
    return __uint_as_float(u);
}
__device__ __forceinline__ void cp_async16(uint32_t dst, const void* src) {
    asm volatile("cp.async.cg.shared.global [%0], [%1], 16;"
                 :: "r"(dst), "l"(src) : "memory");
}
#define CP_COMMIT() asm volatile("cp.async.commit_group;" ::: "memory")
#define CP_WAIT(n)  asm volatile("cp.async.wait_group %0;" :: "n"(n) : "memory")

__device__ __forceinline__ void mma_tf32(float* c, const uint32_t* a, const uint32_t* b) {
    asm volatile(
        "mma.sync.aligned.m16n8k8.row.col.f32.tf32.tf32.f32 "
        "{%0,%1,%2,%3}, {%4,%5,%6,%7}, {%8,%9}, {%0,%1,%2,%3};"
        : "+f"(c[0]), "+f"(c[1]), "+f"(c[2]), "+f"(c[3])
        : "r"(a[0]), "r"(a[1]), "r"(a[2]), "r"(a[3]), "r"(b[0]), "r"(b[1]));
}

// ---------------------------------------------------------------------------
// tf32 round-copy of x
// ---------------------------------------------------------------------------
__global__ void convert_tf32(const float4* __restrict__ in, float4* __restrict__ out, int n4) {
    int i = blockIdx.x * blockDim.x + threadIdx.x;
    if (i < n4) {
        float4 v = in[i];
        v.x = rna_tf32(v.x); v.y = rna_tf32(v.y);
        v.z = rna_tf32(v.z); v.w = rna_tf32(v.w);
        out[i] = v;
    }
}

// ---------------------------------------------------------------------------
// transpose + tf32 round: Wt[n][k] = rna(W[k][n])
// ---------------------------------------------------------------------------
__global__ void transpose1024(const float* __restrict__ W, float* __restrict__ Wt) {
    __shared__ float tile[32][33];
    int x = blockIdx.x * 32 + threadIdx.x;
    int y = blockIdx.y * 32 + threadIdx.y;
#pragma unroll
    for (int j = 0; j < 32; j += 8)
        tile[threadIdx.y + j][threadIdx.x] = W[(size_t)(y + j) * D_ + x];
    __syncthreads();
    x = blockIdx.y * 32 + threadIdx.x;
    y = blockIdx.x * 32 + threadIdx.y;
#pragma unroll
    for (int j = 0; j < 32; j += 8)
        Wt[(size_t)(y + j) * D_ + x] = rna_tf32(tile[threadIdx.x][threadIdx.y + j]);
}

// ---------------------------------------------------------------------------
// TF32 mma.sync GEMM: C[M,1024] = A @ Wt^T + bias   (Wt is [N,K], pre-rounded)
// CTA 128x128, 4 warps (warp tile 64x64), K-stage 32, cp.async double buffer.
// MODE 0: row-major out. MODE 1: head-split scatter [B,H,S,HD].
// ---------------------------------------------------------------------------
#define KS 32
#define NSTAGE (D_ / KS)          // 32
#define PADS 36                   // padded k-stride (floats): bank-conflict-free
#define STAGE_FLOATS (128 * PADS) // 4608 floats = 18KB

template <int MODE>
__global__ __launch_bounds__(128) void gemm_tc(const float* __restrict__ A,
                                               const float* __restrict__ Wt,
                                               const float* __restrict__ bias,
                                               float* __restrict__ C) {
    extern __shared__ float sm[];
    // layout: [A buf0][A buf1][B buf0][B buf1], each STAGE_FLOATS
    const int tid  = threadIdx.x;
    const int wid  = tid >> 5;
    const int lane = tid & 31;
    const int g = lane >> 2;       // 0..7
    const int t = lane & 3;        // 0..3
    const int warp_m = (wid & 1) * 64;
    const int warp_n = (wid >> 1) * 64;
    const int row0 = blockIdx.y * 128;
    const int col0 = blockIdx.x * 128;

    const uint32_t s_u = smem_u32(sm);

    float acc[4][8][4];
#pragma unroll
    for (int mt = 0; mt < 4; mt++)
#pragma unroll
        for (int nt = 0; nt < 8; nt++)
#pragma unroll
            for (int r = 0; r < 4; r++) acc[mt][nt][r] = 0.0f;

    auto issue_stage = [&](int s) {
        const int k0 = s * KS;
        const int buf = s & 1;
        const uint32_t baseA = s_u + (uint32_t)buf * STAGE_FLOATS * 4u;
        const uint32_t baseB = s_u + (uint32_t)(2 + buf) * STAGE_FLOATS * 4u;
#pragma unroll
        for (int i = 0; i < 8; i++) {
            const int lin = tid + i * 128;   // 0..1023
            const int row = lin >> 3;
            const int f4  = (lin & 7) * 4;
            cp_async16(baseA + (uint32_t)(row * PADS + f4) * 4u,
                       &A[(size_t)(row0 + row) * D_ + k0 + f4]);
            cp_async16(baseB + (uint32_t)(row * PADS + f4) * 4u,
                       &Wt[(size_t)(col0 + row) * D_ + k0 + f4]);
        }
        CP_COMMIT();
    };

    issue_stage(0);
    issue_stage(1);

    for (int s = 0; s < NSTAGE; s++) {
        if (s + 1 < NSTAGE) { CP_WAIT(1); } else { CP_WAIT(0); }
        __syncthreads();

        const int buf = s & 1;
        const float* pA = sm + buf * STAGE_FLOATS;
        const float* pB = sm + (2 + buf) * STAGE_FLOATS;

#pragma unroll
        for (int k8 = 0; k8 < 4; k8++) {
            const int kk = k8 * 8 + t;
            uint32_t af[4][4], bf[8][2];
#pragma unroll
            for (int mt = 0; mt < 4; mt++) {
                const int r = warp_m + mt * 16 + g;
                af[mt][0] = __float_as_uint(pA[r * PADS + kk]);
                af[mt][1] = __float_as_uint(pA[(r + 8) * PADS + kk]);
                af[mt][2] = __float_as_uint(pA[r * PADS + kk + 4]);
                af[mt][3] = __float_as_uint(pA[(r + 8) * PADS + kk + 4]);
            }
#pragma unroll
            for (int nt = 0; nt < 8; nt++) {
                const int n = warp_n + nt * 8 + g;
                bf[nt][0] = __float_as_uint(pB[n * PADS + kk]);
                bf[nt][1] = __float_as_uint(pB[n * PADS + kk + 4]);
            }
#pragma unroll
            for (int mt = 0; mt < 4; mt++)
#pragma unroll
                for (int nt = 0; nt < 8; nt++)
                    mma_tf32(acc[mt][nt], af[mt], bf[nt]);
        }
        __syncthreads();
        if (s + 2 < NSTAGE) issue_stage(s + 2);
    }

    // epilogue
#pragma unroll
    for (int mt = 0; mt < 4; mt++) {
        const int r_lo = row0 + warp_m + mt * 16 + g;
#pragma unroll
        for (int nt = 0; nt < 8; nt++) {
            const int cc = col0 + warp_n + nt * 8 + 2 * t;
            const float bx = bias[cc];
            const float by = bias[cc + 1];
            float2 v0 = make_float2(acc[mt][nt][0] + bx, acc[mt][nt][1] + by);
            float2 v1 = make_float2(acc[mt][nt][2] + bx, acc[mt][nt][3] + by);
            if (MODE == 0) {
                *reinterpret_cast<float2*>(&C[(size_t)r_lo * D_ + cc]) = v0;
                *reinterpret_cast<float2*>(&C[(size_t)(r_lo + 8) * D_ + cc]) = v1;
            } else {
                const int hh = cc >> 6;
                const int dd = cc & (HD_ - 1);
                {
                    const int bb = r_lo >> 11;
                    const int ss = r_lo & (S_ - 1);
                    *reinterpret_cast<float2*>(
                        &C[(((size_t)(bb * H_ + hh)) * S_ + ss) * HD_ + dd]) = v0;
                }
                {
                    const int r2 = r_lo + 8;
                    const int bb = r2 >> 11;
                    const int ss = r2 & (S_ - 1);
                    *reinterpret_cast<float2*>(
                        &C[(((size_t)(bb * H_ + hh)) * S_ + ss) * HD_ + dd]) = v1;
                }
            }
        }
    }
}

// ---------------------------------------------------------------------------
// Flash attention (fp32 SIMT) — ctx written tf32-rounded for the final GEMM
// ---------------------------------------------------------------------------
__global__ void attn_kernel(const float* __restrict__ Q,
                            const float* __restrict__ K,
                            const float* __restrict__ V,
                            float* __restrict__ ctx) {
    __shared__ float sQ[64][64];
    __shared__ float sKV[64][64];
    __shared__ float sP[64][64];

    const int tid = threadIdx.x;
    const int tx = tid & 15;
    const int ty = tid >> 4;
    const int qt = blockIdx.x;
    const int h  = blockIdx.y;
    const int b  = blockIdx.z;

    const size_t bh = ((size_t)b * H_ + h) * S_;
    const float* qptr = Q + (bh + (size_t)qt * 64) * HD_;

#pragma unroll
    for (int i = 0; i < 4; i++) {
        const int lin = tid + i * 256;
        const int r = lin >> 4;
        const int c = (lin & 15) * 4;
        *reinterpret_cast<float4*>(&sQ[r][c]) =
            *reinterpret_cast<const float4*>(&qptr[r * HD_ + c]);
    }

    float m[4], l[4], acc[4][4];
#pragma unroll
    for (int r = 0; r < 4; r++) {
        m[r] = -INFINITY;
        l[r] = 0.0f;
#pragma unroll
        for (int c = 0; c < 4; c++) acc[r][c] = 0.0f;
    }

    const float scale = 0.125f;

    for (int kt = 0; kt < S_ / 64; kt++) {
        __syncthreads();
        const float* kptr = K + (bh + (size_t)kt * 64) * HD_;
#pragma unroll
        for (int i = 0; i < 4; i++) {
            const int lin = tid + i * 256;
            const int r = lin >> 4;
            const int c = (lin & 15) * 4;
            float4 kv = *reinterpret_cast<const float4*>(&kptr[r * HD_ + c]);
            sKV[c + 0][r] = kv.x;
            sKV[c + 1][r] = kv.y;
            sKV[c + 2][r] = kv.z;
            sKV[c + 3][r] = kv.w;
        }
        __syncthreads();

        float s[4][4];
#pragma unroll
        for (int r = 0; r < 4; r++)
#pragma unroll
            for (int c = 0; c < 4; c++) s[r][c] = 0.0f;

#pragma unroll 16
        for (int d = 0; d < 64; d++) {
            float a[4], bb[4];
#pragma unroll
            for (int r = 0; r < 4; r++) a[r] = sQ[ty * 4 + r][d];
#pragma unroll
            for (int c = 0; c < 4; c++) bb[c] = sKV[d][tx * 4 + c];
#pragma unroll
            for (int r = 0; r < 4; r++)
#pragma unroll
                for (int c = 0; c < 4; c++) s[r][c] = fmaf(a[r], bb[c], s[r][c]);
        }

        float mnew[4], sc[4], psum[4];
#pragma unroll
        for (int r = 0; r < 4; r++) {
            float v0 = fmaxf(fmaxf(s[r][0], s[r][1]), fmaxf(s[r][2], s[r][3])) * scale;
#pragma unroll
            for (int off = 8; off > 0; off >>= 1)
                v0 = fmaxf(v0, __shfl_xor_sync(0xffffffffu, v0, off, 16));
            mnew[r] = fmaxf(m[r], v0);
            sc[r] = __expf(m[r] - mnew[r]);
            psum[r] = 0.0f;
#pragma unroll
            for (int c = 0; c < 4; c++) {
                const float p = __expf(s[r][c] * scale - mnew[r]);
                sP[ty * 4 + r][tx * 4 + c] = p;
                psum[r] += p;
            }
#pragma unroll
            for (int off = 8; off > 0; off >>= 1)
                psum[r] += __shfl_xor_sync(0xffffffffu, psum[r], off, 16);
            l[r] = l[r] * sc[r] + psum[r];
            m[r] = mnew[r];
#pragma unroll
            for (int c = 0; c < 4; c++) acc[r][c] *= sc[r];
        }
        __syncthreads();

        const float* vptr = V + (bh + (size_t)kt * 64) * HD_;
#pragma unroll
        for (int i = 0; i < 4; i++) {
            const int lin = tid + i * 256;
            const int r = lin >> 4;
            const int c = (lin & 15) * 4;
            *reinterpret_cast<float4*>(&sKV[r][c]) =
                *reinterpret_cast<const float4*>(&vptr[r * HD_ + c]);
        }
        __syncthreads();

#pragma unroll 16
        for (int j = 0; j < 64; j++) {
            float pv[4], vv[4];
#pragma unroll
            for (int r = 0; r < 4; r++) pv[r] = sP[ty * 4 + r][j];
#pragma unroll
            for (int c = 0; c < 4; c++) vv[c] = sKV[j][tx * 4 + c];
#pragma unroll
            for (int r = 0; r < 4; r++)
#pragma unroll
                for (int c = 0; c < 4; c++) acc[r][c] = fmaf(pv[r], vv[c], acc[r][c]);
        }
    }

#pragma unroll
    for (int r = 0; r < 4; r++) {
        const float inv_l = 1.0f / l[r];
        const size_t row = (size_t)b * S_ + (size_t)qt * 64 + ty * 4 + r;
#pragma unroll
        for (int c = 0; c < 4; c++) {
            // tf32-round so the final mma GEMM sees rna-rounded inputs
            ctx[row * D_ + h * HD_ + tx * 4 + c] = rna_tf32(acc[r][c] * inv_l);
        }
    }
}

// ---------------------------------------------------------------------------
extern "C" void kernel_launch(void* const* d_in, const int* in_sizes, int n_in,
                              void* d_out, int out_size) {
    const float* x  = (const float*)d_in[0];
    const float* Wq = (const float*)d_in[1];
    const float* bq = (const float*)d_in[2];
    const float* Wk = (const float*)d_in[3];
    const float* bk = (const float*)d_in[4];
    const float* Wv = (const float*)d_in[5];
    const float* bv = (const float*)d_in[6];
    const float* Wo = (const float*)d_in[7];
    const float* bo = (const float*)d_in[8];
    float* out = (float*)d_out;

    float *q, *k, *v, *ctx, *wt, *xr;
    cudaGetSymbolAddress((void**)&q,   g_q);
    cudaGetSymbolAddress((void**)&k,   g_k);
    cudaGetSymbolAddress((void**)&v,   g_v);
    cudaGetSymbolAddress((void**)&ctx, g_ctx);
    cudaGetSymbolAddress((void**)&wt,  g_wt);
    cudaGetSymbolAddress((void**)&xr,  g_xr);
    float* wtq = wt;
    float* wtk = wt + 1 * D_ * D_;
    float* wtv = wt + 2 * D_ * D_;
    float* wto = wt + 3 * D_ * D_;

    const int smem_bytes = 4 * STAGE_FLOATS * 4;  // 72KB
    cudaFuncSetAttribute(gemm_tc<0>, cudaFuncAttributeMaxDynamicSharedMemorySize, smem_bytes);
    cudaFuncSetAttribute(gemm_tc<1>, cudaFuncAttributeMaxDynamicSharedMemorySize, smem_bytes);

    const int n4 = M_ * D_ / 4;
    convert_tf32<<<(n4 + 255) / 256, 256>>>((const float4*)x, (float4*)xr, n4);

    dim3 tr_grid(32, 32), tr_blk(32, 8);
    transpose1024<<<tr_grid, tr_blk>>>(Wq, wtq);
    transpose1024<<<tr_grid, tr_blk>>>(Wk, wtk);
    transpose1024<<<tr_grid, tr_blk>>>(Wv, wtv);
    transpose1024<<<tr_grid, tr_blk>>>(Wo, wto);

    dim3 gg(D_ / 128, M_ / 128);   // (8, 32)
    gemm_tc<1><<<gg, 128, smem_bytes>>>(xr, wtq, bq, q);
    gemm_tc<1><<<gg, 128, smem_bytes>>>(xr, wtk, bk, k);
    gemm_tc<1><<<gg, 128, smem_bytes>>>(xr, wtv, bv, v);

    dim3 attn_grid(S_ / 64, H_, B_);
    attn_kernel<<<attn_grid, 256>>>(q, k, v, ctx);

    gemm_tc<0><<<gg, 128, smem_bytes>>>(ctx, wto, bo, out);
}

// round 4
// speedup vs baseline: 2.8226x; 1.9101x over previous
#include <cuda_runtime.h>
#include <math.h>
#include <cstdint>

#define D_  1024
#define S_  2048
#define H_  16
#define HD_ 64
#define B_  2
#define M_  (B_ * S_)   // 4096

// Scratch
__device__ float g_q[B_ * H_ * S_ * HD_];
__device__ float g_k[B_ * H_ * S_ * HD_];
__device__ float g_v[B_ * H_ * S_ * HD_];
__device__ float g_ctx[M_ * D_];
__device__ float g_wt[4][D_ * D_];   // transposed + tf32-rounded weights [N,K]
__device__ float g_xr[M_ * D_];      // tf32-rounded x

// ---------------------------------------------------------------------------
// helpers
// ---------------------------------------------------------------------------
__device__ __forceinline__ uint32_t smem_u32(const void* p) {
    uint32_t a;
    asm("{ .reg .u64 t; cvta.to.shared.u64 t, %1; cvt.u32.u64 %0, t; }"
        : "=r"(a) : "l"(p));
    return a;
}
__device__ __forceinline__ float rna_tf32(float x) {
    uint32_t u;
    asm("cvt.rna.tf32.f32 %0, %1;" : "=r"(u) : "f"(x));
    return __uint_as_float(u);
}
__device__ __forceinline__ void cp_async16(uint32_t dst, const void* src) {
    asm volatile("cp.async.cg.shared.global [%0], [%1], 16;"
                 :: "r"(dst), "l"(src) : "memory");
}
#define CP_COMMIT() asm volatile("cp.async.commit_group;" ::: "memory")
#define CP_WAIT(n)  asm volatile("cp.async.wait_group %0;" :: "n"(n) : "memory")

__device__ __forceinline__ void mma_tf32(float* c, const uint32_t* a, const uint32_t* b) {
    asm volatile(
        "mma.sync.aligned.m16n8k8.row.col.f32.tf32.tf32.f32 "
        "{%0,%1,%2,%3}, {%4,%5,%6,%7}, {%8,%9}, {%0,%1,%2,%3};"
        : "+f"(c[0]), "+f"(c[1]), "+f"(c[2]), "+f"(c[3])
        : "r"(a[0]), "r"(a[1]), "r"(a[2]), "r"(a[3]), "r"(b[0]), "r"(b[1]));
}

// ---------------------------------------------------------------------------
// tf32 round-copy of x
// ---------------------------------------------------------------------------
__global__ void convert_tf32(const float4* __restrict__ in, float4* __restrict__ out, int n4) {
    int i = blockIdx.x * blockDim.x + threadIdx.x;
    if (i < n4) {
        float4 v = in[i];
        v.x = rna_tf32(v.x); v.y = rna_tf32(v.y);
        v.z = rna_tf32(v.z); v.w = rna_tf32(v.w);
        out[i] = v;
    }
}

// ---------------------------------------------------------------------------
// transpose + tf32 round: Wt[n][k] = rna(W[k][n])
// ---------------------------------------------------------------------------
__global__ void transpose1024(const float* __restrict__ W, float* __restrict__ Wt) {
    __shared__ float tile[32][33];
    int x = blockIdx.x * 32 + threadIdx.x;
    int y = blockIdx.y * 32 + threadIdx.y;
#pragma unroll
    for (int j = 0; j < 32; j += 8)
        tile[threadIdx.y + j][threadIdx.x] = W[(size_t)(y + j) * D_ + x];
    __syncthreads();
    x = blockIdx.y * 32 + threadIdx.x;
    y = blockIdx.x * 32 + threadIdx.y;
#pragma unroll
    for (int j = 0; j < 32; j += 8)
        Wt[(size_t)(y + j) * D_ + x] = rna_tf32(tile[threadIdx.x][threadIdx.y + j]);
}

// ---------------------------------------------------------------------------
// TF32 mma.sync GEMM: C[M,1024] = A @ Wt^T + bias   (Wt is [N,K], pre-rounded)
// CTA 128x128, 4 warps, K-stage 32, cp.async double buffer.
// MODE 0: row-major out, exact fp32 result.
// MODE 1: head-split scatter [B,H,S,HD], writes rna_tf32((acc+bias)*mult).
// ---------------------------------------------------------------------------
#define KS 32
#define NSTAGE (D_ / KS)          // 32
#define PADS 36
#define STAGE_FLOATS (128 * PADS)

template <int MODE>
__global__ __launch_bounds__(128) void gemm_tc(const float* __restrict__ A,
                                               const float* __restrict__ Wt,
                                               const float* __restrict__ bias,
                                               float* __restrict__ C,
                                               float mult) {
    extern __shared__ float sm[];
    const int tid  = threadIdx.x;
    const int wid  = tid >> 5;
    const int lane = tid & 31;
    const int g = lane >> 2;
    const int t = lane & 3;
    const int warp_m = (wid & 1) * 64;
    const int warp_n = (wid >> 1) * 64;
    const int row0 = blockIdx.y * 128;
    const int col0 = blockIdx.x * 128;

    const uint32_t s_u = smem_u32(sm);

    float acc[4][8][4];
#pragma unroll
    for (int mt = 0; mt < 4; mt++)
#pragma unroll
        for (int nt = 0; nt < 8; nt++)
#pragma unroll
            for (int r = 0; r < 4; r++) acc[mt][nt][r] = 0.0f;

    auto issue_stage = [&](int s) {
        const int k0 = s * KS;
        const int buf = s & 1;
        const uint32_t baseA = s_u + (uint32_t)buf * STAGE_FLOATS * 4u;
        const uint32_t baseB = s_u + (uint32_t)(2 + buf) * STAGE_FLOATS * 4u;
#pragma unroll
        for (int i = 0; i < 8; i++) {
            const int lin = tid + i * 128;
            const int row = lin >> 3;
            const int f4  = (lin & 7) * 4;
            cp_async16(baseA + (uint32_t)(row * PADS + f4) * 4u,
                       &A[(size_t)(row0 + row) * D_ + k0 + f4]);
            cp_async16(baseB + (uint32_t)(row * PADS + f4) * 4u,
                       &Wt[(size_t)(col0 + row) * D_ + k0 + f4]);
        }
        CP_COMMIT();
    };

    issue_stage(0);
    issue_stage(1);

    for (int s = 0; s < NSTAGE; s++) {
        if (s + 1 < NSTAGE) { CP_WAIT(1); } else { CP_WAIT(0); }
        __syncthreads();

        const int buf = s & 1;
        const float* pA = sm + buf * STAGE_FLOATS;
        const float* pB = sm + (2 + buf) * STAGE_FLOATS;

#pragma unroll
        for (int k8 = 0; k8 < 4; k8++) {
            const int kk = k8 * 8 + t;
            uint32_t af[4][4], bf[8][2];
#pragma unroll
            for (int mt = 0; mt < 4; mt++) {
                const int r = warp_m + mt * 16 + g;
                af[mt][0] = __float_as_uint(pA[r * PADS + kk]);
                af[mt][1] = __float_as_uint(pA[(r + 8) * PADS + kk]);
                af[mt][2] = __float_as_uint(pA[r * PADS + kk + 4]);
                af[mt][3] = __float_as_uint(pA[(r + 8) * PADS + kk + 4]);
            }
#pragma unroll
            for (int nt = 0; nt < 8; nt++) {
                const int n = warp_n + nt * 8 + g;
                bf[nt][0] = __float_as_uint(pB[n * PADS + kk]);
                bf[nt][1] = __float_as_uint(pB[n * PADS + kk + 4]);
            }
#pragma unroll
            for (int mt = 0; mt < 4; mt++)
#pragma unroll
                for (int nt = 0; nt < 8; nt++)
                    mma_tf32(acc[mt][nt], af[mt], bf[nt]);
        }
        __syncthreads();
        if (s + 2 < NSTAGE) issue_stage(s + 2);
    }

#pragma unroll
    for (int mt = 0; mt < 4; mt++) {
        const int r_lo = row0 + warp_m + mt * 16 + g;
#pragma unroll
        for (int nt = 0; nt < 8; nt++) {
            const int cc = col0 + warp_n + nt * 8 + 2 * t;
            const float bx = bias[cc];
            const float by = bias[cc + 1];
            float2 v0, v1;
            if (MODE == 0) {
                v0 = make_float2(acc[mt][nt][0] + bx, acc[mt][nt][1] + by);
                v1 = make_float2(acc[mt][nt][2] + bx, acc[mt][nt][3] + by);
                *reinterpret_cast<float2*>(&C[(size_t)r_lo * D_ + cc]) = v0;
                *reinterpret_cast<float2*>(&C[(size_t)(r_lo + 8) * D_ + cc]) = v1;
            } else {
                v0 = make_float2(rna_tf32((acc[mt][nt][0] + bx) * mult),
                                 rna_tf32((acc[mt][nt][1] + by) * mult));
                v1 = make_float2(rna_tf32((acc[mt][nt][2] + bx) * mult),
                                 rna_tf32((acc[mt][nt][3] + by) * mult));
                const int hh = cc >> 6;
                const int dd = cc & (HD_ - 1);
                {
                    const int bb = r_lo >> 11;
                    const int ss = r_lo & (S_ - 1);
                    *reinterpret_cast<float2*>(
                        &C[(((size_t)(bb * H_ + hh)) * S_ + ss) * HD_ + dd]) = v0;
                }
                {
                    const int r2 = r_lo + 8;
                    const int bb = r2 >> 11;
                    const int ss = r2 & (S_ - 1);
                    *reinterpret_cast<float2*>(
                        &C[(((size_t)(bb * H_ + hh)) * S_ + ss) * HD_ + dd]) = v1;
                }
            }
        }
    }
}

// ---------------------------------------------------------------------------
// Tensor-core flash attention (tf32 mma.sync).
// CTA = (64-q tile, h, b); 4 warps; warp w owns q rows [16w, 16w+16).
// Q pre-scaled by 0.125 and tf32-rounded (projection epilogue).
// K/V tf32-rounded; cp.async double-buffered raw copies.
// ---------------------------------------------------------------------------
#define AT_PAD 68
#define KV_FLOATS (64 * AT_PAD)          // one K or V tile

__global__ __launch_bounds__(128) void attn_tc(const float* __restrict__ Q,
                                               const float* __restrict__ K,
                                               const float* __restrict__ V,
                                               float* __restrict__ ctx) {
    extern __shared__ float sa[];
    // layout: K0 K1 V0 V1 P[4 warps][16*AT_PAD]
    const int tid  = threadIdx.x;
    const int wid  = tid >> 5;
    const int lane = tid & 31;
    const int g = lane >> 2;
    const int t = lane & 3;
    const int qt = blockIdx.x;
    const int h  = blockIdx.y;
    const int b  = blockIdx.z;
    const size_t bh = ((size_t)b * H_ + h) * S_;
    const int q0 = qt * 64;

    float* sKbuf = sa;
    float* sVbuf = sa + 2 * KV_FLOATS;
    float* sPw   = sa + 4 * KV_FLOATS + wid * 16 * AT_PAD;

    // Q fragments in registers (once per CTA)
    const float* Qp = Q + (bh + q0 + wid * 16) * HD_;
    uint32_t qf[8][4];
#pragma unroll
    for (int kt = 0; kt < 8; kt++) {
        qf[kt][0] = __float_as_uint(Qp[g * HD_ + kt * 8 + t]);
        qf[kt][1] = __float_as_uint(Qp[(g + 8) * HD_ + kt * 8 + t]);
        qf[kt][2] = __float_as_uint(Qp[g * HD_ + kt * 8 + t + 4]);
        qf[kt][3] = __float_as_uint(Qp[(g + 8) * HD_ + kt * 8 + t + 4]);
    }

    float o[8][4];
#pragma unroll
    for (int nt = 0; nt < 8; nt++)
#pragma unroll
        for (int r = 0; r < 4; r++) o[nt][r] = 0.0f;
    float m0 = -INFINITY, m1 = -INFINITY, l0 = 0.0f, l1 = 0.0f;

    auto load_tile = [&](int i, int buf) {
        const float* Kp = K + (bh + (size_t)i * 64) * HD_;
        const float* Vp = V + (bh + (size_t)i * 64) * HD_;
        const uint32_t dK = smem_u32(sKbuf + buf * KV_FLOATS);
        const uint32_t dV = smem_u32(sVbuf + buf * KV_FLOATS);
#pragma unroll
        for (int j = 0; j < 8; j++) {
            const int lin = tid + j * 128;
            const int row = lin >> 4;
            const int f4  = (lin & 15) * 4;
            cp_async16(dK + (uint32_t)(row * AT_PAD + f4) * 4u, Kp + row * HD_ + f4);
            cp_async16(dV + (uint32_t)(row * AT_PAD + f4) * 4u, Vp + row * HD_ + f4);
        }
        CP_COMMIT();
    };

    load_tile(0, 0);

    for (int i = 0; i < S_ / 64; i++) {
        if (i + 1 < S_ / 64) { load_tile(i + 1, (i + 1) & 1); CP_WAIT(1); }
        else { CP_WAIT(0); }
        __syncthreads();
        const float* sK = sKbuf + (i & 1) * KV_FLOATS;
        const float* sV = sVbuf + (i & 1) * KV_FLOATS;

        // QK^T scores (already scaled via pre-scaled Q)
        float s[8][4];
#pragma unroll
        for (int nt = 0; nt < 8; nt++)
#pragma unroll
            for (int r = 0; r < 4; r++) s[nt][r] = 0.0f;
#pragma unroll
        for (int kt = 0; kt < 8; kt++) {
#pragma unroll
            for (int nt = 0; nt < 8; nt++) {
                uint32_t bf[2];
                bf[0] = __float_as_uint(sK[(nt * 8 + g) * AT_PAD + kt * 8 + t]);
                bf[1] = __float_as_uint(sK[(nt * 8 + g) * AT_PAD + kt * 8 + t + 4]);
                mma_tf32(s[nt], qf[kt], bf);
            }
        }

        // online softmax (rows g and g+8; each row lives on one lane-quad)
        float mx0 = -INFINITY, mx1 = -INFINITY;
#pragma unroll
        for (int nt = 0; nt < 8; nt++) {
            mx0 = fmaxf(mx0, fmaxf(s[nt][0], s[nt][1]));
            mx1 = fmaxf(mx1, fmaxf(s[nt][2], s[nt][3]));
        }
        mx0 = fmaxf(mx0, __shfl_xor_sync(0xffffffffu, mx0, 1));
        mx0 = fmaxf(mx0, __shfl_xor_sync(0xffffffffu, mx0, 2));
        mx1 = fmaxf(mx1, __shfl_xor_sync(0xffffffffu, mx1, 1));
        mx1 = fmaxf(mx1, __shfl_xor_sync(0xffffffffu, mx1, 2));
        const float mn0 = fmaxf(m0, mx0);
        const float mn1 = fmaxf(m1, mx1);
        const float f0 = __expf(m0 - mn0);
        const float f1 = __expf(m1 - mn1);
        m0 = mn0; m1 = mn1;

        float s0 = 0.0f, s1 = 0.0f;
#pragma unroll
        for (int nt = 0; nt < 8; nt++) {
            const float p00 = rna_tf32(__expf(s[nt][0] - mn0));
            const float p01 = rna_tf32(__expf(s[nt][1] - mn0));
            const float p10 = rna_tf32(__expf(s[nt][2] - mn1));
            const float p11 = rna_tf32(__expf(s[nt][3] - mn1));
            s0 += p00 + p01;
            s1 += p10 + p11;
            *reinterpret_cast<float2*>(&sPw[g * AT_PAD + nt * 8 + 2 * t]) =
                make_float2(p00, p01);
            *reinterpret_cast<float2*>(&sPw[(g + 8) * AT_PAD + nt * 8 + 2 * t]) =
                make_float2(p10, p11);
        }
        s0 += __shfl_xor_sync(0xffffffffu, s0, 1);
        s0 += __shfl_xor_sync(0xffffffffu, s0, 2);
        s1 += __shfl_xor_sync(0xffffffffu, s1, 1);
        s1 += __shfl_xor_sync(0xffffffffu, s1, 2);
        l0 = l0 * f0 + s0;
        l1 = l1 * f1 + s1;
#pragma unroll
        for (int nt = 0; nt < 8; nt++) {
            o[nt][0] *= f0; o[nt][1] *= f0;
            o[nt][2] *= f1; o[nt][3] *= f1;
        }
        __syncwarp();

        // P @ V
#pragma unroll
        for (int kt = 0; kt < 8; kt++) {
            uint32_t af[4];
            af[0] = __float_as_uint(sPw[g * AT_PAD + kt * 8 + t]);
            af[1] = __float_as_uint(sPw[(g + 8) * AT_PAD + kt * 8 + t]);
            af[2] = __float_as_uint(sPw[g * AT_PAD + kt * 8 + t + 4]);
            af[3] = __float_as_uint(sPw[(g + 8) * AT_PAD + kt * 8 + t + 4]);
#pragma unroll
            for (int nt = 0; nt < 8; nt++) {
                uint32_t bf[2];
                bf[0] = __float_as_uint(sV[(kt * 8 + t) * AT_PAD + nt * 8 + g]);
                bf[1] = __float_as_uint(sV[(kt * 8 + t + 4) * AT_PAD + nt * 8 + g]);
                mma_tf32(o[nt], af, bf);
            }
        }
        __syncthreads();
    }

    // epilogue: ctx rows, rna-rounded for the final GEMM
    const float inv0 = 1.0f / l0;
    const float inv1 = 1.0f / l1;
    const size_t row_lo = (size_t)b * S_ + q0 + wid * 16 + g;
#pragma unroll
    for (int nt = 0; nt < 8; nt++) {
        const int col = h * HD_ + nt * 8 + 2 * t;
        *reinterpret_cast<float2*>(&ctx[row_lo * D_ + col]) =
            make_float2(rna_tf32(o[nt][0] * inv0), rna_tf32(o[nt][1] * inv0));
        *reinterpret_cast<float2*>(&ctx[(row_lo + 8) * D_ + col]) =
            make_float2(rna_tf32(o[nt][2] * inv1), rna_tf32(o[nt][3] * inv1));
    }
}

// ---------------------------------------------------------------------------
extern "C" void kernel_launch(void* const* d_in, const int* in_sizes, int n_in,
                              void* d_out, int out_size) {
    const float* x  = (const float*)d_in[0];
    const float* Wq = (const float*)d_in[1];
    const float* bq = (const float*)d_in[2];
    const float* Wk = (const float*)d_in[3];
    const float* bk = (const float*)d_in[4];
    const float* Wv = (const float*)d_in[5];
    const float* bv = (const float*)d_in[6];
    const float* Wo = (const float*)d_in[7];
    const float* bo = (const float*)d_in[8];
    float* out = (float*)d_out;

    float *q, *k, *v, *ctx, *wt, *xr;
    cudaGetSymbolAddress((void**)&q,   g_q);
    cudaGetSymbolAddress((void**)&k,   g_k);
    cudaGetSymbolAddress((void**)&v,   g_v);
    cudaGetSymbolAddress((void**)&ctx, g_ctx);
    cudaGetSymbolAddress((void**)&wt,  g_wt);
    cudaGetSymbolAddress((void**)&xr,  g_xr);
    float* wtq = wt;
    float* wtk = wt + 1 * D_ * D_;
    float* wtv = wt + 2 * D_ * D_;
    float* wto = wt + 3 * D_ * D_;

    const int gemm_smem = 4 * STAGE_FLOATS * 4;           // 72KB
    const int attn_smem = (4 * KV_FLOATS + 4 * 16 * AT_PAD) * 4;  // 85KB
    cudaFuncSetAttribute(gemm_tc<0>, cudaFuncAttributeMaxDynamicSharedMemorySize, gemm_smem);
    cudaFuncSetAttribute(gemm_tc<1>, cudaFuncAttributeMaxDynamicSharedMemorySize, gemm_smem);
    cudaFuncSetAttribute(attn_tc, cudaFuncAttributeMaxDynamicSharedMemorySize, attn_smem);

    const int n4 = M_ * D_ / 4;
    convert_tf32<<<(n4 + 255) / 256, 256>>>((const float4*)x, (float4*)xr, n4);

    dim3 tr_grid(32, 32), tr_blk(32, 8);
    transpose1024<<<tr_grid, tr_blk>>>(Wq, wtq);
    transpose1024<<<tr_grid, tr_blk>>>(Wk, wtk);
    transpose1024<<<tr_grid, tr_blk>>>(Wv, wtv);
    transpose1024<<<tr_grid, tr_blk>>>(Wo, wto);

    dim3 gg(D_ / 128, M_ / 128);   // (8, 32)
    gemm_tc<1><<<gg, 128, gemm_smem>>>(xr, wtq, bq, q, 0.125f);  // Q pre-scaled
    gemm_tc<1><<<gg, 128, gemm_smem>>>(xr, wtk, bk, k, 1.0f);
    gemm_tc<1><<<gg, 128, gemm_smem>>>(xr, wtv, bv, v, 1.0f);

    dim3 attn_grid(S_ / 64, H_, B_);
    attn_tc<<<attn_grid, 128, attn_smem>>>(q, k, v, ctx);

    gemm_tc<0><<<gg, 128, gemm_smem>>>(ctx, wto, bo, out, 1.0f);
}

// round 6
// speedup vs baseline: 6.9780x; 2.4722x over previous
#include <cuda_runtime.h>
#include <cuda_fp16.h>
#include <math.h>
#include <cstdint>

#define D_  1024
#define S_  2048
#define H_  16
#define HD_ 64
#define B_  2
#define M_  (B_ * S_)   // 4096

// Scratch (half precision activations/weights)
__device__ __half g_xh[M_ * D_];          // x in fp16
__device__ __half g_q[B_ * H_ * S_ * HD_]; // [B,H,S,HD], pre-scaled by 0.125
__device__ __half g_k[B_ * H_ * S_ * HD_]; // [B,H,S,HD]
__device__ __half g_v[B_ * H_ * HD_ * S_]; // [B,H,HD,S]  (transposed!)
__device__ __half g_ctx[M_ * D_];          // [B,S,D]
__device__ __half g_wt[4][D_ * D_];        // transposed weights [N,K] fp16

// ---------------------------------------------------------------------------
// helpers
// ---------------------------------------------------------------------------
__device__ __forceinline__ uint32_t smem_u32(const void* p) {
    uint32_t a;
    asm("{ .reg .u64 t; cvta.to.shared.u64 t, %1; cvt.u32.u64 %0, t; }"
        : "=r"(a) : "l"(p));
    return a;
}
__device__ __forceinline__ uint32_t h2_as_u32(__half2 h) {
    return *reinterpret_cast<uint32_t*>(&h);
}
__device__ __forceinline__ void cp_async16(uint32_t dst, const void* src) {
    asm volatile("cp.async.cg.shared.global [%0], [%1], 16;"
                 :: "r"(dst), "l"(src) : "memory");
}
#define CP_COMMIT() asm volatile("cp.async.commit_group;" ::: "memory")
#define CP_WAIT(n)  asm volatile("cp.async.wait_group %0;" :: "n"(n) : "memory")

// m16n8k16 fp16 MMA, fp32 accumulate
__device__ __forceinline__ void mma_f16(float* c, const uint32_t* a, const uint32_t* b) {
    asm volatile(
        "mma.sync.aligned.m16n8k16.row.col.f32.f16.f16.f32 "
        "{%0,%1,%2,%3}, {%4,%5,%6,%7}, {%8,%9}, {%0,%1,%2,%3};"
        : "+f"(c[0]), "+f"(c[1]), "+f"(c[2]), "+f"(c[3])
        : "r"(a[0]), "r"(a[1]), "r"(a[2]), "r"(a[3]), "r"(b[0]), "r"(b[1]));
}

// ---------------------------------------------------------------------------
// x: fp32 -> fp16
// ---------------------------------------------------------------------------
__global__ void f32_to_f16(const float4* __restrict__ in, __half2* __restrict__ out, int n4) {
    int i = blockIdx.x * blockDim.x + threadIdx.x;
    if (i < n4) {
        float4 v = in[i];
        out[2 * i]     = __floats2half2_rn(v.x, v.y);
        out[2 * i + 1] = __floats2half2_rn(v.z, v.w);
    }
}

// ---------------------------------------------------------------------------
// transpose + fp16: Wt[n][k] = half(W[k][n])
// ---------------------------------------------------------------------------
__global__ void transpose1024(const float* __restrict__ W, __half* __restrict__ Wt) {
    __shared__ float tile[32][33];
    int x = blockIdx.x * 32 + threadIdx.x;
    int y = blockIdx.y * 32 + threadIdx.y;
#pragma unroll
    for (int j = 0; j < 32; j += 8)
        tile[threadIdx.y + j][threadIdx.x] = W[(size_t)(y + j) * D_ + x];
    __syncthreads();
    x = blockIdx.y * 32 + threadIdx.x;
    y = blockIdx.x * 32 + threadIdx.y;
#pragma unroll
    for (int j = 0; j < 32; j += 8)
        Wt[(size_t)(y + j) * D_ + x] = __float2half(tile[threadIdx.x][threadIdx.y + j]);
}

// ---------------------------------------------------------------------------
// fp16 mma GEMM: C[M,1024] = A @ Wt^T + bias   (A, Wt fp16; Wt is [N,K])
// CTA 128x128, 4 warps (warp tile 64x64), K-stage 64, cp.async double buffer.
// MODE 0: fp32 row-major out
// MODE 1: half out, head-split [B,H,S,HD], value (acc+bias)*mult
// MODE 2: half out, transposed head-split [B,H,HD,S]
// ---------------------------------------------------------------------------
#define KS 64
#define NSTAGE (D_ / KS)          // 16
#define PADH 72                   // padded k-stride in halves
#define STAGE_H (128 * PADH)      // halves per buffer

template <int MODE>
__global__ __launch_bounds__(128) void gemm_f16(const __half* __restrict__ A,
                                                const __half* __restrict__ Wt,
                                                const float* __restrict__ bias,
                                                void* __restrict__ Cout,
                                                float mult) {
    extern __shared__ __half smh[];
    const int tid  = threadIdx.x;
    const int wid  = tid >> 5;
    const int lane = tid & 31;
    const int g = lane >> 2;
    const int t = lane & 3;
    const int warp_m = (wid & 1) * 64;
    const int warp_n = (wid >> 1) * 64;
    const int row0 = blockIdx.y * 128;
    const int col0 = blockIdx.x * 128;

    const uint32_t s_u = smem_u32(smh);

    float acc[4][8][4];
#pragma unroll
    for (int mt = 0; mt < 4; mt++)
#pragma unroll
        for (int nt = 0; nt < 8; nt++)
#pragma unroll
            for (int r = 0; r < 4; r++) acc[mt][nt][r] = 0.0f;

    auto issue_stage = [&](int s) {
        const int k0 = s * KS;
        const int buf = s & 1;
        const uint32_t baseA = s_u + (uint32_t)buf * STAGE_H * 2u;
        const uint32_t baseB = s_u + (uint32_t)(2 + buf) * STAGE_H * 2u;
#pragma unroll
        for (int i = 0; i < 8; i++) {
            const int lin = tid + i * 128;       // 0..1023
            const int row = lin >> 3;            // 0..127
            const int f8  = (lin & 7) * 8;       // half index, 16B chunks
            cp_async16(baseA + (uint32_t)(row * PADH + f8) * 2u,
                       &A[(size_t)(row0 + row) * D_ + k0 + f8]);
            cp_async16(baseB + (uint32_t)(row * PADH + f8) * 2u,
                       &Wt[(size_t)(col0 + row) * D_ + k0 + f8]);
        }
        CP_COMMIT();
    };

    issue_stage(0);
    issue_stage(1);

    for (int s = 0; s < NSTAGE; s++) {
        if (s + 1 < NSTAGE) { CP_WAIT(1); } else { CP_WAIT(0); }
        __syncthreads();

        const int buf = s & 1;
        const __half* pA = smh + buf * STAGE_H;
        const __half* pB = smh + (2 + buf) * STAGE_H;

#pragma unroll
        for (int k16 = 0; k16 < 4; k16++) {
            const int kk = k16 * 16 + 2 * t;
            uint32_t af[4][4], bf[8][2];
#pragma unroll
            for (int mt = 0; mt < 4; mt++) {
                const int r = warp_m + mt * 16 + g;
                af[mt][0] = *reinterpret_cast<const uint32_t*>(&pA[r * PADH + kk]);
                af[mt][1] = *reinterpret_cast<const uint32_t*>(&pA[(r + 8) * PADH + kk]);
                af[mt][2] = *reinterpret_cast<const uint32_t*>(&pA[r * PADH + kk + 8]);
                af[mt][3] = *reinterpret_cast<const uint32_t*>(&pA[(r + 8) * PADH + kk + 8]);
            }
#pragma unroll
            for (int nt = 0; nt < 8; nt++) {
                const int n = warp_n + nt * 8 + g;
                bf[nt][0] = *reinterpret_cast<const uint32_t*>(&pB[n * PADH + kk]);
                bf[nt][1] = *reinterpret_cast<const uint32_t*>(&pB[n * PADH + kk + 8]);
            }
#pragma unroll
            for (int mt = 0; mt < 4; mt++)
#pragma unroll
                for (int nt = 0; nt < 8; nt++)
                    mma_f16(acc[mt][nt], af[mt], bf[nt]);
        }
        __syncthreads();
        if (s + 2 < NSTAGE) issue_stage(s + 2);
    }

    // epilogue
#pragma unroll
    for (int mt = 0; mt < 4; mt++) {
        const int r_lo = row0 + warp_m + mt * 16 + g;
#pragma unroll
        for (int nt = 0; nt < 8; nt++) {
            const int cc = col0 + warp_n + nt * 8 + 2 * t;
            const float bx = bias[cc];
            const float by = bias[cc + 1];
#pragma unroll
            for (int half_ = 0; half_ < 2; half_++) {
                const int rr = r_lo + half_ * 8;
                const float v0 = acc[mt][nt][2 * half_ + 0] + bx;
                const float v1 = acc[mt][nt][2 * half_ + 1] + by;
                if (MODE == 0) {
                    float* C = (float*)Cout;
                    *reinterpret_cast<float2*>(&C[(size_t)rr * D_ + cc]) =
                        make_float2(v0, v1);
                } else if (MODE == 1) {
                    __half* C = (__half*)Cout;
                    const int bb = rr >> 11;
                    const int ss = rr & (S_ - 1);
                    const int hh = cc >> 6;
                    const int dd = cc & (HD_ - 1);
                    *reinterpret_cast<__half2*>(
                        &C[(((size_t)(bb * H_ + hh)) * S_ + ss) * HD_ + dd]) =
                        __floats2half2_rn(v0 * mult, v1 * mult);
                } else {
                    __half* C = (__half*)Cout;
                    const int bb = rr >> 11;
                    const int ss = rr & (S_ - 1);
                    const int hh = cc >> 6;
                    const int dd = cc & (HD_ - 1);
                    C[(((size_t)(bb * H_ + hh)) * HD_ + dd) * S_ + ss] = __float2half(v0);
                    C[(((size_t)(bb * H_ + hh)) * HD_ + dd + 1) * S_ + ss] = __float2half(v1);
                }
            }
        }
    }
}

// ---------------------------------------------------------------------------
// fp16 tensor-core flash attention.
// CTA = (64-q tile, h, b); 4 warps; warp w owns q rows [16w, 16w+16).
// Q pre-scaled by 0.125 (projection epilogue). V is [B,H,HD,S].
// P stays in registers (accumulator layout == A-fragment layout).
// ---------------------------------------------------------------------------
#define PADA 72
#define TILE_H (64 * PADA)   // halves per K or Vt tile

__global__ __launch_bounds__(128) void attn_f16(const __half* __restrict__ Q,
                                                const __half* __restrict__ K,
                                                const __half* __restrict__ V,
                                                __half* __restrict__ ctx) {
    extern __shared__ __half sah[];
    // layout: K0 K1 Vt0 Vt1, each TILE_H halves
    const int tid  = threadIdx.x;
    const int wid  = tid >> 5;
    const int lane = tid & 31;
    const int g = lane >> 2;
    const int t = lane & 3;
    const int qt = blockIdx.x;
    const int h  = blockIdx.y;
    const int b  = blockIdx.z;
    const size_t bh = ((size_t)b * H_ + h);
    const int q0 = qt * 64;

    __half* sK  = sah;
    __half* sVt = sah + 2 * TILE_H;

    // Q fragments in registers (4 k16-steps over HD=64)
    const __half* Qp = Q + (bh * S_ + q0 + wid * 16) * HD_;
    uint32_t qf[4][4];
#pragma unroll
    for (int kt = 0; kt < 4; kt++) {
        const int kk = kt * 16 + 2 * t;
        qf[kt][0] = *reinterpret_cast<const uint32_t*>(&Qp[g * HD_ + kk]);
        qf[kt][1] = *reinterpret_cast<const uint32_t*>(&Qp[(g + 8) * HD_ + kk]);
        qf[kt][2] = *reinterpret_cast<const uint32_t*>(&Qp[g * HD_ + kk + 8]);
        qf[kt][3] = *reinterpret_cast<const uint32_t*>(&Qp[(g + 8) * HD_ + kk + 8]);
    }

    float o[8][4];
#pragma unroll
    for (int nt = 0; nt < 8; nt++)
#pragma unroll
        for (int r = 0; r < 4; r++) o[nt][r] = 0.0f;
    float m0 = -INFINITY, m1 = -INFINITY, l0 = 0.0f, l1 = 0.0f;

    const __half* Kbase = K + bh * S_ * HD_;
    const __half* Vbase = V + bh * (size_t)HD_ * S_;

    auto load_tile = [&](int i, int buf) {
        const __half* Kp = Kbase + (size_t)i * 64 * HD_;
        const uint32_t dK = smem_u32(sK + buf * TILE_H);
        const uint32_t dV = smem_u32(sVt + buf * TILE_H);
#pragma unroll
        for (int j = 0; j < 4; j++) {
            const int lin = tid + j * 128;   // 0..511
            const int row = lin >> 3;        // 0..63
            const int f8  = (lin & 7) * 8;   // halves
            cp_async16(dK + (uint32_t)(row * PADA + f8) * 2u, Kp + row * HD_ + f8);
            cp_async16(dV + (uint32_t)(row * PADA + f8) * 2u,
                       Vbase + (size_t)row * S_ + i * 64 + f8);
        }
        CP_COMMIT();
    };

    load_tile(0, 0);

    for (int i = 0; i < S_ / 64; i++) {
        if (i + 1 < S_ / 64) { load_tile(i + 1, (i + 1) & 1); CP_WAIT(1); }
        else { CP_WAIT(0); }
        __syncthreads();
        const __half* cK = sK  + (i & 1) * TILE_H;
        const __half* cV = sVt + (i & 1) * TILE_H;

        // scores = Q_scaled @ K^T
        float s[8][4];
#pragma unroll
        for (int nt = 0; nt < 8; nt++)
#pragma unroll
            for (int r = 0; r < 4; r++) s[nt][r] = 0.0f;
#pragma unroll
        for (int kt = 0; kt < 4; kt++) {
            const int kk = kt * 16 + 2 * t;
#pragma unroll
            for (int nt = 0; nt < 8; nt++) {
                uint32_t bf[2];
                bf[0] = *reinterpret_cast<const uint32_t*>(&cK[(nt * 8 + g) * PADA + kk]);
                bf[1] = *reinterpret_cast<const uint32_t*>(&cK[(nt * 8 + g) * PADA + kk + 8]);
                mma_f16(s[nt], qf[kt], bf);
            }
        }

        // online softmax (rows g and g+8; row data lives on one lane-quad)
        float mx0 = -INFINITY, mx1 = -INFINITY;
#pragma unroll
        for (int nt = 0; nt < 8; nt++) {
            mx0 = fmaxf(mx0, fmaxf(s[nt][0], s[nt][1]));
            mx1 = fmaxf(mx1, fmaxf(s[nt][2], s[nt][3]));
        }
        mx0 = fmaxf(mx0, __shfl_xor_sync(0xffffffffu, mx0, 1));
        mx0 = fmaxf(mx0, __shfl_xor_sync(0xffffffffu, mx0, 2));
        mx1 = fmaxf(mx1, __shfl_xor_sync(0xffffffffu, mx1, 1));
        mx1 = fmaxf(mx1, __shfl_xor_sync(0xffffffffu, mx1, 2));
        const float mn0 = fmaxf(m0, mx0);
        const float mn1 = fmaxf(m1, mx1);
        const float f0 = __expf(m0 - mn0);
        const float f1 = __expf(m1 - mn1);
        m0 = mn0; m1 = mn1;

        float s0 = 0.0f, s1 = 0.0f;
#pragma unroll
        for (int nt = 0; nt < 8; nt++) {
            s[nt][0] = __expf(s[nt][0] - mn0);
            s[nt][1] = __expf(s[nt][1] - mn0);
            s[nt][2] = __expf(s[nt][2] - mn1);
            s[nt][3] = __expf(s[nt][3] - mn1);
            s0 += s[nt][0] + s[nt][1];
            s1 += s[nt][2] + s[nt][3];
        }
        s0 += __shfl_xor_sync(0xffffffffu, s0, 1);
        s0 += __shfl_xor_sync(0xffffffffu, s0, 2);
        s1 += __shfl_xor_sync(0xffffffffu, s1, 1);
        s1 += __shfl_xor_sync(0xffffffffu, s1, 2);
        l0 = l0 * f0 + s0;
        l1 = l1 * f1 + s1;
#pragma unroll
        for (int nt = 0; nt < 8; nt++) {
            o[nt][0] *= f0; o[nt][1] *= f0;
            o[nt][2] *= f1; o[nt][3] *= f1;
        }

        // P @ V : P packed in-register (accumulator layout == A-fragment layout)
#pragma unroll
        for (int kt = 0; kt < 4; kt++) {
            uint32_t pa[4];
            pa[0] = h2_as_u32(__floats2half2_rn(s[2 * kt][0],     s[2 * kt][1]));
            pa[1] = h2_as_u32(__floats2half2_rn(s[2 * kt][2],     s[2 * kt][3]));
            pa[2] = h2_as_u32(__floats2half2_rn(s[2 * kt + 1][0], s[2 * kt + 1][1]));
            pa[3] = h2_as_u32(__floats2half2_rn(s[2 * kt + 1][2], s[2 * kt + 1][3]));
            const int kk = kt * 16 + 2 * t;
#pragma unroll
            for (int nt = 0; nt < 8; nt++) {
                uint32_t bf[2];
                bf[0] = *reinterpret_cast<const uint32_t*>(&cV[(nt * 8 + g) * PADA + kk]);
                bf[1] = *reinterpret_cast<const uint32_t*>(&cV[(nt * 8 + g) * PADA + kk + 8]);
                mma_f16(o[nt], pa, bf);
            }
        }
        __syncthreads();
    }

    // epilogue: ctx half [B,S,D]
    const float inv0 = 1.0f / l0;
    const float inv1 = 1.0f / l1;
    const size_t row_lo = (size_t)b * S_ + q0 + wid * 16 + g;
#pragma unroll
    for (int nt = 0; nt < 8; nt++) {
        const int col = h * HD_ + nt * 8 + 2 * t;
        *reinterpret_cast<__half2*>(&ctx[row_lo * D_ + col]) =
            __floats2half2_rn(o[nt][0] * inv0, o[nt][1] * inv0);
        *reinterpret_cast<__half2*>(&ctx[(row_lo + 8) * D_ + col]) =
            __floats2half2_rn(o[nt][2] * inv1, o[nt][3] * inv1);
    }
}

// ---------------------------------------------------------------------------
extern "C" void kernel_launch(void* const* d_in, const int* in_sizes, int n_in,
                              void* d_out, int out_size) {
    const float* x  = (const float*)d_in[0];
    const float* Wq = (const float*)d_in[1];
    const float* bq = (const float*)d_in[2];
    const float* Wk = (const float*)d_in[3];
    const float* bk = (const float*)d_in[4];
    const float* Wv = (const float*)d_in[5];
    const float* bv = (const float*)d_in[6];
    const float* Wo = (const float*)d_in[7];
    const float* bo = (const float*)d_in[8];
    float* out = (float*)d_out;

    __half *xh, *q, *k, *v, *ctx, *wt;
    cudaGetSymbolAddress((void**)&xh,  g_xh);
    cudaGetSymbolAddress((void**)&q,   g_q);
    cudaGetSymbolAddress((void**)&k,   g_k);
    cudaGetSymbolAddress((void**)&v,   g_v);
    cudaGetSymbolAddress((void**)&ctx, g_ctx);
    cudaGetSymbolAddress((void**)&wt,  g_wt);
    __half* wtq = wt;
    __half* wtk = wt + 1 * D_ * D_;
    __half* wtv = wt + 2 * D_ * D_;
    __half* wto = wt + 3 * D_ * D_;

    const int gemm_smem = 4 * STAGE_H * 2;     // 73728 B
    const int attn_smem = 4 * TILE_H * 2;      // 36864 B
    cudaFuncSetAttribute(gemm_f16<0>, cudaFuncAttributeMaxDynamicSharedMemorySize, gemm_smem);
    cudaFuncSetAttribute(gemm_f16<1>, cudaFuncAttributeMaxDynamicSharedMemorySize, gemm_smem);
    cudaFuncSetAttribute(gemm_f16<2>, cudaFuncAttributeMaxDynamicSharedMemorySize, gemm_smem);
    cudaFuncSetAttribute(attn_f16, cudaFuncAttributeMaxDynamicSharedMemorySize, attn_smem);

    const int n4 = M_ * D_ / 4;
    f32_to_f16<<<(n4 + 255) / 256, 256>>>((const float4*)x, (__half2*)xh, n4);

    dim3 tr_grid(32, 32), tr_blk(32, 8);
    transpose1024<<<tr_grid, tr_blk>>>(Wq, wtq);
    transpose1024<<<tr_grid, tr_blk>>>(Wk, wtk);
    transpose1024<<<tr_grid, tr_blk>>>(Wv, wtv);
    transpose1024<<<tr_grid, tr_blk>>>(Wo, wto);

    dim3 gg(D_ / 128, M_ / 128);   // (8, 32)
    gemm_f16<1><<<gg, 128, gemm_smem>>>(xh, wtq, bq, q, 0.125f);  // Q pre-scaled
    gemm_f16<1><<<gg, 128, gemm_smem>>>(xh, wtk, bk, k, 1.0f);
    gemm_f16<2><<<gg, 128, gemm_smem>>>(xh, wtv, bv, v, 1.0f);    // V transposed

    dim3 attn_grid(S_ / 64, H_, B_);
    attn_f16<<<attn_grid, 128, attn_smem>>>(q, k, v, ctx);

    gemm_f16<0><<<gg, 128, gemm_smem>>>(ctx, wto, bo, out, 1.0f);
}